// round 7
// baseline (speedup 1.0000x reference)
#include <cuda_runtime.h>
#include <cuda_fp16.h>

// Problem constants
#define NB 16            // batch B
#define TT 12            // T_IN
#define TO 24            // T_TOTAL
#define NN 5000          // nodes
#define CC 4             // channels
#define KK 16            // neighbors
#define HH 4             // heads
#define BT (NB * TT)     // 192
#define DOUT (TO - TT)   // 12
#define NT 2             // nodes per block (main kernel)
#define THREADS 128

typedef unsigned long long u64;

// Scratch: x as fp16, dt-interleaved: g_xt3[n][dt][b*4+tq] = (c01,c23) of
// bt = b*12 + 3*tq + dt.  8B entries, 7.68 MB total, L2-resident.
__device__ uint2 g_xt3[NN * 192];

static __device__ __forceinline__ float2 h2f(unsigned u) {
    __half2 h = *reinterpret_cast<__half2*>(&u);
    return __half22float2(h);
}
static __device__ __forceinline__ u64 pk(float lo, float hi) {
    u64 r;
    asm("mov.b64 %0, {%1, %2};" : "=l"(r) : "f"(lo), "f"(hi));
    return r;
}
static __device__ __forceinline__ u64 pkh(unsigned u) {   // fp16x2 -> packed f32x2
    float2 f = h2f(u);
    return pk(f.x, f.y);
}
static __device__ __forceinline__ u64 fma2(u64 a, u64 b, u64 c) {
    u64 d;
    asm("fma.rn.f32x2 %0, %1, %2, %3;" : "=l"(d) : "l"(a), "l"(b), "l"(c));
    return d;
}
static __device__ __forceinline__ u64 add2(u64 a, u64 b) {
    u64 d;
    asm("add.rn.f32x2 %0, %1, %2;" : "=l"(d) : "l"(a), "l"(b));
    return d;
}
static __device__ __forceinline__ float2 upk(u64 v) {
    float2 f;
    asm("mov.b64 {%0, %1}, %2;" : "=f"(f.x), "=f"(f.y) : "l"(v));
    return f;
}

// ---------------------------------------------------------------------------
// Kernel 1: x [B,T,N,C] f32 -> g_xt3 (fp16, dt-interleaved)  AND out[:, :12] = x
// 16 nodes per block, 512 threads (16 n x 32 slots).
// ---------------------------------------------------------------------------
__global__ void __launch_bounds__(512) transpose_convert_kernel(
    const float* __restrict__ x, float* __restrict__ out)
{
    __shared__ uint2 tile[BT][17];            // [bt][n_local], pad 17: 26.1KB
    const float4* __restrict__ x4 = (const float4*)x;
    float4* __restrict__ out4 = (float4*)out;

    const int tx = threadIdx.x;               // 0..15 : n_local
    const int ty = threadIdx.y;               // 0..31
    const int n0 = blockIdx.x * 16;
    const int n  = n0 + tx;

    if (n < NN) {
        #pragma unroll
        for (int s = 0; s < 6; ++s) {
            int bt = s * 32 + ty;
            float4 v = x4[bt * NN + n];
            __half2 h01 = __floats2half2_rn(v.x, v.y);
            __half2 h23 = __floats2half2_rn(v.z, v.w);
            uint2 u;
            u.x = *reinterpret_cast<unsigned*>(&h01);
            u.y = *reinterpret_cast<unsigned*>(&h23);
            tile[bt][tx] = u;
            int b = bt / TT, t = bt - b * TT;
            out4[(b * TO + t) * NN + n] = v;   // out[:, :12] = x (coalesced)
        }
    }
    __syncthreads();

    const int tid  = ty * 16 + tx;             // 0..511
    const int n_l  = tid >> 5;                 // 0..15 (warp-uniform)
    const int lane = tid & 31;
    if (n0 + n_l < NN) {
        #pragma unroll
        for (int it = 0; it < 6; ++it) {
            int uidx = it * 32 + lane;          // 0..191 : [dt][b*4+tq]
            int dt = uidx >> 6, r = uidx & 63;
            int b = r >> 2, tq = r & 3;
            int bt = b * TT + 3 * tq + dt;
            g_xt3[(n0 + n_l) * 192 + uidx] = tile[bt][n_l];
        }
    }
}

// ---------------------------------------------------------------------------
// Kernel 2: per node-pair, fully register-resident.
//   thread = (nl, b, tq): gathers+aggregates its t-triple, computes output
//   partials in registers, butterfly-reduces over the 4 tq lanes, stages
//   stores through a small smem buffer for coalesced STG.
// ---------------------------------------------------------------------------
__global__ void __launch_bounds__(THREADS, 4) gnn_main_kernel(
    const float* __restrict__ dists, const int* __restrict__ neighbors,
    const float* __restrict__ W, const float* __restrict__ bias,
    float* __restrict__ out)
{
    __shared__ ulonglong2 Wpk[48 * 7];        // row = (dt*4+h)*4+tq, 6 op cols + pad
    __shared__ ulonglong2 wp_s[NT][KK][2];    // packed gaussian weights
    __shared__ int   nbr_s[NT][KK];
    __shared__ float b_s[DOUT];
    __shared__ __align__(16) float ys[192 * 12];  // cell (b*12+o): 2 nodes x float4 + pad

    const int tid = threadIdx.x;              // 0..127
    const int n0  = blockIdx.x * NT;
    const int nl  = tid >> 6;                 // warp-uniform
    const int g   = tid & 63;
    const int b   = g >> 2;
    const int tq  = g & 3;

    // --- Phase 0 ---
    if (tid < NT * KK) {
        int nn = tid >> 4, k = tid & 15;
        float d = dists[(n0 + nn) * KK + k];
        nbr_s[nn][k] = neighbors[(n0 + nn) * KK + k];
        float p = d * d * (1.0f / 36.0f);     // d^2 / sigma^2
        float w0 = __expf(-0.25f * p);
        float w1 = __expf(-0.50f * p);
        float w2 = __expf(-0.75f * p);
        float w3 = __expf(-p);
        wp_s[nn][k][0] = make_ulonglong2(pk(w0, w0), pk(w1, w1));
        wp_s[nn][k][1] = make_ulonglong2(pk(w2, w2), pk(w3, w3));
    }
    #pragma unroll
    for (int i = tid; i < 48 * 6; i += THREADS) {
        int row = i / 6, op = i - row * 6;
        int tq_ = row & 3, dh = row >> 2;      // dh = dt*4+h
        int dt = dh >> 2, h = dh & 3;
        int th = (3 * tq_ + dt) * HH + h;
        float w0 = W[th * DOUT + op * 2];
        float w1 = W[th * DOUT + op * 2 + 1];
        Wpk[row * 7 + op] = make_ulonglong2(pk(w0, w0), pk(w1, w1));
    }
    if (tid < DOUT) b_s[tid] = bias[tid];
    __syncthreads();

    // --- Phase 1: gather + weighted aggregation, all in registers ---
    u64 acc[3][HH][2];                         // [dt][h][c01|c23]
    #pragma unroll
    for (int dt = 0; dt < 3; ++dt)
        #pragma unroll
        for (int h = 0; h < HH; ++h) { acc[dt][h][0] = 0ULL; acc[dt][h][1] = 0ULL; }

    #pragma unroll
    for (int k = 0; k < KK; ++k) {
        int base = nbr_s[nl][k] * 192 + g;
        uint2 v0 = g_xt3[base];                // dt=0 : dense 256B per warp
        uint2 v1 = g_xt3[base + 64];           // dt=1
        uint2 v2 = g_xt3[base + 128];          // dt=2
        ulonglong2 wA = wp_s[nl][k][0];        // (w0,w0),(w1,w1)
        ulonglong2 wB = wp_s[nl][k][1];        // (w2,w2),(w3,w3)
        u64 x01, x23;
        x01 = pkh(v0.x); x23 = pkh(v0.y);
        acc[0][0][0] = fma2(x01, wA.x, acc[0][0][0]);
        acc[0][0][1] = fma2(x23, wA.x, acc[0][0][1]);
        acc[0][1][0] = fma2(x01, wA.y, acc[0][1][0]);
        acc[0][1][1] = fma2(x23, wA.y, acc[0][1][1]);
        acc[0][2][0] = fma2(x01, wB.x, acc[0][2][0]);
        acc[0][2][1] = fma2(x23, wB.x, acc[0][2][1]);
        acc[0][3][0] = fma2(x01, wB.y, acc[0][3][0]);
        acc[0][3][1] = fma2(x23, wB.y, acc[0][3][1]);
        x01 = pkh(v1.x); x23 = pkh(v1.y);
        acc[1][0][0] = fma2(x01, wA.x, acc[1][0][0]);
        acc[1][0][1] = fma2(x23, wA.x, acc[1][0][1]);
        acc[1][1][0] = fma2(x01, wA.y, acc[1][1][0]);
        acc[1][1][1] = fma2(x23, wA.y, acc[1][1][1]);
        acc[1][2][0] = fma2(x01, wB.x, acc[1][2][0]);
        acc[1][2][1] = fma2(x23, wB.x, acc[1][2][1]);
        acc[1][3][0] = fma2(x01, wB.y, acc[1][3][0]);
        acc[1][3][1] = fma2(x23, wB.y, acc[1][3][1]);
        x01 = pkh(v2.x); x23 = pkh(v2.y);
        acc[2][0][0] = fma2(x01, wA.x, acc[2][0][0]);
        acc[2][0][1] = fma2(x23, wA.x, acc[2][0][1]);
        acc[2][1][0] = fma2(x01, wA.y, acc[2][1][0]);
        acc[2][1][1] = fma2(x23, wA.y, acc[2][1][1]);
        acc[2][2][0] = fma2(x01, wB.x, acc[2][2][0]);
        acc[2][2][1] = fma2(x23, wB.x, acc[2][2][1]);
        acc[2][3][0] = fma2(x01, wB.y, acc[2][3][0]);
        acc[2][3][1] = fma2(x23, wB.y, acc[2][3][1]);
    }

    // --- Phase 2: output partials in registers, two o-halves, shuffle-reduce ---
    #pragma unroll
    for (int Hh = 0; Hh < 2; ++Hh) {
        u64 y[12];                             // y[o_loc*2 + cp], o_loc 0..5
        #pragma unroll
        for (int ol = 0; ol < 6; ++ol) {
            float bv = (tq == 0) ? b_s[Hh * 6 + ol] : 0.f;  // bias once per group
            u64 pb = pk(bv, bv);
            y[ol * 2] = pb; y[ol * 2 + 1] = pb;
        }
        #pragma unroll
        for (int dt = 0; dt < 3; ++dt) {
            #pragma unroll
            for (int h = 0; h < HH; ++h) {
                u64 a01 = acc[dt][h][0], a23 = acc[dt][h][1];
                const ulonglong2* wrow = &Wpk[((dt * 4 + h) * 4 + tq) * 7 + Hh * 3];
                #pragma unroll
                for (int op = 0; op < 3; ++op) {
                    ulonglong2 w = wrow[op];   // conflict-free 4-distinct broadcast
                    y[op * 4 + 0] = fma2(a01, w.x, y[op * 4 + 0]);
                    y[op * 4 + 1] = fma2(a23, w.x, y[op * 4 + 1]);
                    y[op * 4 + 2] = fma2(a01, w.y, y[op * 4 + 2]);
                    y[op * 4 + 3] = fma2(a23, w.y, y[op * 4 + 3]);
                }
            }
        }

        // Butterfly reduce-scatter over the 4 tq lanes.
        // Set A = o_loc {0,2,4} (y idx 0,1,4,5,8,9); B = {1,3,5} (idx 2,3,6,7,10,11)
        u64 z[6];
        const bool oddl = (tq & 1);
        #pragma unroll
        for (int i = 0; i < 6; ++i) {
            int ia = (i >> 1) * 4 + (i & 1);
            int ib = ia + 2;
            u64 tA = __shfl_xor_sync(0xffffffffu, y[ia], 1);
            u64 tB = __shfl_xor_sync(0xffffffffu, y[ib], 1);
            z[i] = oddl ? add2(y[ib], tB) : add2(y[ia], tA);
        }
        #pragma unroll
        for (int i = 0; i < 6; ++i) {
            u64 t = __shfl_xor_sync(0xffffffffu, z[i], 2);
            z[i] = add2(z[i], t);
        }
        // lanes: tq0 -> o_loc 0 and 2; tq1 -> 1 and 3; tq2 -> 4; tq3 -> 5
        {
            int o1 = (tq < 2) ? tq : (tq + 2);
            int zi = (tq < 2) ? 0 : 4;
            float2 f01 = upk(z[zi]), f23 = upk(z[zi + 1]);
            float4 v;
            v.x = fmaxf(f01.x, 0.f); v.y = fmaxf(f01.y, 0.f);
            v.z = fmaxf(f23.x, 0.f); v.w = fmaxf(f23.y, 0.f);
            *(float4*)&ys[(b * DOUT + Hh * 6 + o1) * 12 + nl * 4] = v;
            if (tq < 2) {
                float2 g01 = upk(z[2]), g23 = upk(z[3]);
                float4 v2;
                v2.x = fmaxf(g01.x, 0.f); v2.y = fmaxf(g01.y, 0.f);
                v2.z = fmaxf(g23.x, 0.f); v2.w = fmaxf(g23.y, 0.f);
                *(float4*)&ys[(b * DOUT + Hh * 6 + tq + 2) * 12 + nl * 4] = v2;
            }
        }
    }
    __syncthreads();

    // --- Coalesced cooperative store: 192 cells x 2 nodes ---
    float4* __restrict__ out4 = (float4*)out;
    #pragma unroll
    for (int it = 0; it < 3; ++it) {
        int idx = it * THREADS + tid;          // 0..383
        int c = idx >> 1, j = idx & 1;         // c = b*12+o, j = node
        float4 v = *(const float4*)&ys[c * 12 + j * 4];
        int bb = c / DOUT, oo = c - bb * DOUT;
        out4[(bb * TO + TT + oo) * NN + n0 + j] = v;
    }
}

// ---------------------------------------------------------------------------
// metadata order: x (f32), dists (f32), W (f32), b (f32), neighbors (i32);
// output f32 (7680000)
// ---------------------------------------------------------------------------
extern "C" void kernel_launch(void* const* d_in, const int* in_sizes, int n_in,
                              void* d_out, int out_size)
{
    const float* x         = (const float*)d_in[0];
    const float* dists     = (const float*)d_in[1];
    const float* W         = (const float*)d_in[2];
    const float* bias      = (const float*)d_in[3];
    const int*   neighbors = (const int*)d_in[4];
    float* out = (float*)d_out;

    dim3 tb(16, 32);
    transpose_convert_kernel<<<(NN + 15) / 16, tb>>>(x, out);

    gnn_main_kernel<<<NN / NT, THREADS>>>(dists, neighbors, W, bias, out);
}

// round 8
// speedup vs baseline: 1.0414x; 1.0414x over previous
#include <cuda_runtime.h>
#include <cuda_fp16.h>

// Problem constants
#define NB 16            // batch B
#define TT 12            // T_IN
#define TO 24            // T_TOTAL
#define NN 5000          // nodes
#define CC 4             // channels
#define KK 16            // neighbors
#define HH 4             // heads
#define BT (NB * TT)     // 192
#define DOUT (TO - TT)   // 12
#define NT 2             // nodes per block (main kernel)
#define THREADS 128

typedef unsigned long long u64;

// Scratch: x as fp16, dt-interleaved: g_xt3[n][dt][b*4+tq] = (c01,c23) of
// bt = b*12 + 3*tq + dt.  8B entries, 7.68 MB total, L2-resident.
__device__ uint2 g_xt3[NN * 192];

static __device__ __forceinline__ float2 h2f(unsigned u) {
    __half2 h = *reinterpret_cast<__half2*>(&u);
    return __half22float2(h);
}
static __device__ __forceinline__ u64 pk(float lo, float hi) {
    u64 r;
    asm("mov.b64 %0, {%1, %2};" : "=l"(r) : "f"(lo), "f"(hi));
    return r;
}
static __device__ __forceinline__ u64 pkh(unsigned u) {   // fp16x2 -> packed f32x2
    float2 f = h2f(u);
    return pk(f.x, f.y);
}
static __device__ __forceinline__ u64 fma2(u64 a, u64 b, u64 c) {
    u64 d;
    asm("fma.rn.f32x2 %0, %1, %2, %3;" : "=l"(d) : "l"(a), "l"(b), "l"(c));
    return d;
}
static __device__ __forceinline__ u64 add2(u64 a, u64 b) {
    u64 d;
    asm("add.rn.f32x2 %0, %1, %2;" : "=l"(d) : "l"(a), "l"(b));
    return d;
}
static __device__ __forceinline__ float2 upk(u64 v) {
    float2 f;
    asm("mov.b64 {%0, %1}, %2;" : "=f"(f.x), "=f"(f.y) : "l"(v));
    return f;
}

// ---------------------------------------------------------------------------
// Kernel 1: x [B,T,N,C] f32 -> g_xt3 (fp16, dt-interleaved)  AND out[:, :12] = x
// 16 nodes per block, 512 threads (16 n x 32 slots).
// ---------------------------------------------------------------------------
__global__ void __launch_bounds__(512) transpose_convert_kernel(
    const float* __restrict__ x, float* __restrict__ out)
{
    __shared__ uint2 tile[BT][17];            // [bt][n_local], pad 17: 26.1KB
    const float4* __restrict__ x4 = (const float4*)x;
    float4* __restrict__ out4 = (float4*)out;

    const int tx = threadIdx.x;               // 0..15 : n_local
    const int ty = threadIdx.y;               // 0..31
    const int n0 = blockIdx.x * 16;
    const int n  = n0 + tx;

    if (n < NN) {
        #pragma unroll
        for (int s = 0; s < 6; ++s) {
            int bt = s * 32 + ty;
            float4 v = x4[bt * NN + n];
            __half2 h01 = __floats2half2_rn(v.x, v.y);
            __half2 h23 = __floats2half2_rn(v.z, v.w);
            uint2 u;
            u.x = *reinterpret_cast<unsigned*>(&h01);
            u.y = *reinterpret_cast<unsigned*>(&h23);
            tile[bt][tx] = u;
            int b = bt / TT, t = bt - b * TT;
            out4[(b * TO + t) * NN + n] = v;   // out[:, :12] = x (coalesced)
        }
    }
    __syncthreads();

    const int tid  = ty * 16 + tx;             // 0..511
    const int n_l  = tid >> 5;                 // 0..15 (warp-uniform)
    const int lane = tid & 31;
    if (n0 + n_l < NN) {
        #pragma unroll
        for (int it = 0; it < 6; ++it) {
            int uidx = it * 32 + lane;          // 0..191 : [dt][b*4+tq]
            int dt = uidx >> 6, r = uidx & 63;
            int b = r >> 2, tq = r & 3;
            int bt = b * TT + 3 * tq + dt;
            g_xt3[(n0 + n_l) * 192 + uidx] = tile[bt][n_l];
        }
    }
}

// ---------------------------------------------------------------------------
// Kernel 2: per node-pair, fully register-resident.
//   thread = (nl, b, tq): gathers+aggregates its t-triple, computes output
//   partials in registers, butterfly-reduces over the 4 tq lanes, stages
//   stores through a small smem buffer for coalesced STG.
// ---------------------------------------------------------------------------
__global__ void __launch_bounds__(THREADS, 4) gnn_main_kernel(
    const float* __restrict__ dists, const int* __restrict__ neighbors,
    const float* __restrict__ W, const float* __restrict__ bias,
    float* __restrict__ out)
{
    __shared__ ulonglong2 Wpk[48 * 7];        // row = (dt*4+h)*4+tq, 6 op cols + pad
    __shared__ ulonglong2 wp_s[NT][KK][2];    // packed gaussian weights
    __shared__ int   nbr_s[NT][KK];
    __shared__ float b_s[DOUT];
    __shared__ __align__(16) float ys[192 * 12];  // cell (b*12+o): 2 nodes x float4 + pad

    const int tid = threadIdx.x;              // 0..127
    const int n0  = blockIdx.x * NT;
    const int nl  = tid >> 6;                 // warp-uniform
    const int g   = tid & 63;
    const int b   = g >> 2;
    const int tq  = g & 3;

    // --- Phase 0 ---
    if (tid < NT * KK) {
        int nn = tid >> 4, k = tid & 15;
        float d = dists[(n0 + nn) * KK + k];
        nbr_s[nn][k] = neighbors[(n0 + nn) * KK + k];
        float p = d * d * (1.0f / 36.0f);     // d^2 / sigma^2
        float w0 = __expf(-0.25f * p);
        float w1 = __expf(-0.50f * p);
        float w2 = __expf(-0.75f * p);
        float w3 = __expf(-p);
        wp_s[nn][k][0] = make_ulonglong2(pk(w0, w0), pk(w1, w1));
        wp_s[nn][k][1] = make_ulonglong2(pk(w2, w2), pk(w3, w3));
    }
    #pragma unroll
    for (int i = tid; i < 48 * 6; i += THREADS) {
        int row = i / 6, op = i - row * 6;
        int tq_ = row & 3, dh = row >> 2;      // dh = dt*4+h
        int dt = dh >> 2, h = dh & 3;
        int th = (3 * tq_ + dt) * HH + h;
        float w0 = W[th * DOUT + op * 2];
        float w1 = W[th * DOUT + op * 2 + 1];
        Wpk[row * 7 + op] = make_ulonglong2(pk(w0, w0), pk(w1, w1));
    }
    if (tid < DOUT) b_s[tid] = bias[tid];
    __syncthreads();

    // --- Phase 1: gather + weighted aggregation, all in registers ---
    u64 acc[3][HH][2];                         // [dt][h][c01|c23]
    #pragma unroll
    for (int dt = 0; dt < 3; ++dt)
        #pragma unroll
        for (int h = 0; h < HH; ++h) { acc[dt][h][0] = 0ULL; acc[dt][h][1] = 0ULL; }

    #pragma unroll
    for (int k = 0; k < KK; ++k) {
        int base = nbr_s[nl][k] * 192 + g;
        uint2 v0 = g_xt3[base];                // dt=0 : dense 256B per warp
        uint2 v1 = g_xt3[base + 64];           // dt=1
        uint2 v2 = g_xt3[base + 128];          // dt=2
        ulonglong2 wA = wp_s[nl][k][0];        // (w0,w0),(w1,w1)
        ulonglong2 wB = wp_s[nl][k][1];        // (w2,w2),(w3,w3)
        u64 x01, x23;
        x01 = pkh(v0.x); x23 = pkh(v0.y);
        acc[0][0][0] = fma2(x01, wA.x, acc[0][0][0]);
        acc[0][0][1] = fma2(x23, wA.x, acc[0][0][1]);
        acc[0][1][0] = fma2(x01, wA.y, acc[0][1][0]);
        acc[0][1][1] = fma2(x23, wA.y, acc[0][1][1]);
        acc[0][2][0] = fma2(x01, wB.x, acc[0][2][0]);
        acc[0][2][1] = fma2(x23, wB.x, acc[0][2][1]);
        acc[0][3][0] = fma2(x01, wB.y, acc[0][3][0]);
        acc[0][3][1] = fma2(x23, wB.y, acc[0][3][1]);
        x01 = pkh(v1.x); x23 = pkh(v1.y);
        acc[1][0][0] = fma2(x01, wA.x, acc[1][0][0]);
        acc[1][0][1] = fma2(x23, wA.x, acc[1][0][1]);
        acc[1][1][0] = fma2(x01, wA.y, acc[1][1][0]);
        acc[1][1][1] = fma2(x23, wA.y, acc[1][1][1]);
        acc[1][2][0] = fma2(x01, wB.x, acc[1][2][0]);
        acc[1][2][1] = fma2(x23, wB.x, acc[1][2][1]);
        acc[1][3][0] = fma2(x01, wB.y, acc[1][3][0]);
        acc[1][3][1] = fma2(x23, wB.y, acc[1][3][1]);
        x01 = pkh(v2.x); x23 = pkh(v2.y);
        acc[2][0][0] = fma2(x01, wA.x, acc[2][0][0]);
        acc[2][0][1] = fma2(x23, wA.x, acc[2][0][1]);
        acc[2][1][0] = fma2(x01, wA.y, acc[2][1][0]);
        acc[2][1][1] = fma2(x23, wA.y, acc[2][1][1]);
        acc[2][2][0] = fma2(x01, wB.x, acc[2][2][0]);
        acc[2][2][1] = fma2(x23, wB.x, acc[2][2][1]);
        acc[2][3][0] = fma2(x01, wB.y, acc[2][3][0]);
        acc[2][3][1] = fma2(x23, wB.y, acc[2][3][1]);
    }

    // --- Phase 2: output partials in registers, two o-halves, shuffle-reduce ---
    #pragma unroll
    for (int Hh = 0; Hh < 2; ++Hh) {
        u64 y[12];                             // y[o_loc*2 + cp], o_loc 0..5
        #pragma unroll
        for (int ol = 0; ol < 6; ++ol) {
            float bv = (tq == 0) ? b_s[Hh * 6 + ol] : 0.f;  // bias once per group
            u64 pb = pk(bv, bv);
            y[ol * 2] = pb; y[ol * 2 + 1] = pb;
        }
        #pragma unroll
        for (int dt = 0; dt < 3; ++dt) {
            #pragma unroll
            for (int h = 0; h < HH; ++h) {
                u64 a01 = acc[dt][h][0], a23 = acc[dt][h][1];
                const ulonglong2* wrow = &Wpk[((dt * 4 + h) * 4 + tq) * 7 + Hh * 3];
                #pragma unroll
                for (int op = 0; op < 3; ++op) {
                    ulonglong2 w = wrow[op];   // conflict-free 4-distinct broadcast
                    y[op * 4 + 0] = fma2(a01, w.x, y[op * 4 + 0]);
                    y[op * 4 + 1] = fma2(a23, w.x, y[op * 4 + 1]);
                    y[op * 4 + 2] = fma2(a01, w.y, y[op * 4 + 2]);
                    y[op * 4 + 3] = fma2(a23, w.y, y[op * 4 + 3]);
                }
            }
        }

        // Butterfly reduce-scatter over the 4 tq lanes.
        // Set A = o_loc {0,2,4} (y idx 0,1,4,5,8,9); B = {1,3,5} (idx 2,3,6,7,10,11)
        u64 z[6];
        const bool oddl = (tq & 1);
        #pragma unroll
        for (int i = 0; i < 6; ++i) {
            int ia = (i >> 1) * 4 + (i & 1);
            int ib = ia + 2;
            u64 tA = __shfl_xor_sync(0xffffffffu, y[ia], 1);
            u64 tB = __shfl_xor_sync(0xffffffffu, y[ib], 1);
            z[i] = oddl ? add2(y[ib], tB) : add2(y[ia], tA);
        }
        #pragma unroll
        for (int i = 0; i < 6; ++i) {
            u64 t = __shfl_xor_sync(0xffffffffu, z[i], 2);
            z[i] = add2(z[i], t);
        }
        // lanes: tq0 -> o_loc 0 and 2; tq1 -> 1 and 3; tq2 -> 4; tq3 -> 5
        {
            int o1 = (tq < 2) ? tq : (tq + 2);
            int zi = (tq < 2) ? 0 : 4;
            float2 f01 = upk(z[zi]), f23 = upk(z[zi + 1]);
            float4 v;
            v.x = fmaxf(f01.x, 0.f); v.y = fmaxf(f01.y, 0.f);
            v.z = fmaxf(f23.x, 0.f); v.w = fmaxf(f23.y, 0.f);
            *(float4*)&ys[(b * DOUT + Hh * 6 + o1) * 12 + nl * 4] = v;
            if (tq < 2) {
                float2 g01 = upk(z[2]), g23 = upk(z[3]);
                float4 v2;
                v2.x = fmaxf(g01.x, 0.f); v2.y = fmaxf(g01.y, 0.f);
                v2.z = fmaxf(g23.x, 0.f); v2.w = fmaxf(g23.y, 0.f);
                *(float4*)&ys[(b * DOUT + Hh * 6 + tq + 2) * 12 + nl * 4] = v2;
            }
        }
    }
    __syncthreads();

    // --- Coalesced cooperative store: 192 cells x 2 nodes ---
    float4* __restrict__ out4 = (float4*)out;
    #pragma unroll
    for (int it = 0; it < 3; ++it) {
        int idx = it * THREADS + tid;          // 0..383
        int c = idx >> 1, j = idx & 1;         // c = b*12+o, j = node
        float4 v = *(const float4*)&ys[c * 12 + j * 4];
        int bb = c / DOUT, oo = c - bb * DOUT;
        out4[(bb * TO + TT + oo) * NN + n0 + j] = v;
    }
}

// ---------------------------------------------------------------------------
// metadata order: x (f32), dists (f32), W (f32), b (f32), neighbors (i32);
// output f32 (7680000)
// ---------------------------------------------------------------------------
extern "C" void kernel_launch(void* const* d_in, const int* in_sizes, int n_in,
                              void* d_out, int out_size)
{
    const float* x         = (const float*)d_in[0];
    const float* dists     = (const float*)d_in[1];
    const float* W         = (const float*)d_in[2];
    const float* bias      = (const float*)d_in[3];
    const int*   neighbors = (const int*)d_in[4];
    float* out = (float*)d_out;

    dim3 tb(16, 32);
    transpose_convert_kernel<<<(NN + 15) / 16, tb>>>(x, out);

    gnn_main_kernel<<<NN / NT, THREADS>>>(dists, neighbors, W, bias, out);
}

// round 9
// speedup vs baseline: 1.2266x; 1.1778x over previous
#include <cuda_runtime.h>
#include <cuda_fp16.h>

// Problem constants
#define NB 16            // batch B
#define TT 12            // T_IN
#define TO 24            // T_TOTAL
#define NN 5000          // nodes
#define CC 4             // channels
#define KK 16            // neighbors
#define HH 4             // heads
#define BT (NB * TT)     // 192
#define BTP (BT / 2)     // 96 bt-pairs
#define DIN (TT * HH)    // 48
#define DOUT (TO - TT)   // 12
#define NT 2             // nodes per block
#define THREADS 256
#define A_STRIDE 56      // halves per A row (112B = 7*16B -> conflict-free ldmatrix)

typedef unsigned long long u64;

// Scratch: x transposed+converted to fp16: [N][btp][8 halfs]. 7.68 MB, L2-resident.
__device__ uint4 g_xt[NN * BTP];

static __device__ __forceinline__ float2 h2f(unsigned u) {
    __half2 h = *reinterpret_cast<__half2*>(&u);
    return __half22float2(h);
}
static __device__ __forceinline__ u64 pk(float lo, float hi) {
    u64 r;
    asm("mov.b64 %0, {%1, %2};" : "=l"(r) : "f"(lo), "f"(hi));
    return r;
}
static __device__ __forceinline__ u64 fma2(u64 a, u64 b, u64 c) {
    u64 d;
    asm("fma.rn.f32x2 %0, %1, %2, %3;" : "=l"(d) : "l"(a), "l"(b), "l"(c));
    return d;
}
static __device__ __forceinline__ float2 upk(u64 v) {
    float2 f;
    asm("mov.b64 {%0, %1}, %2;" : "=f"(f.x), "=f"(f.y) : "l"(v));
    return f;
}
static __device__ __forceinline__ unsigned sm32(const void* p) {
    return (unsigned)__cvta_generic_to_shared(p);
}

// ---------------------------------------------------------------------------
// Kernel 1: x [B,T,N,C] f32 -> xt [N][btp] fp16 (transposed)  AND out[:, :12] = x
// ---------------------------------------------------------------------------
__global__ void __launch_bounds__(1024) transpose_convert_kernel(
    const float* __restrict__ x, float* __restrict__ out)
{
    __shared__ uint2 tile[32][33];
    const float4* __restrict__ x4 = (const float4*)x;
    float4* __restrict__ out4 = (float4*)out;

    int tx = threadIdx.x, ty = threadIdx.y;
    int n  = blockIdx.x * 32 + tx;
    int bt = blockIdx.y * 32 + ty;          // gridDim.y*32 == 192 exactly

    if (n < NN) {
        float4 v = x4[bt * NN + n];
        __half2 h01 = __floats2half2_rn(v.x, v.y);
        __half2 h23 = __floats2half2_rn(v.z, v.w);
        uint2 u;
        u.x = *reinterpret_cast<unsigned*>(&h01);
        u.y = *reinterpret_cast<unsigned*>(&h23);
        tile[ty][tx] = u;
        int b = bt / TT, t = bt - b * TT;
        out4[(b * TO + t) * NN + n] = v;    // out[:, :12] = x (coalesced)
    }
    __syncthreads();

    if (tx < 16) {
        int n2 = blockIdx.x * 32 + ty;
        if (n2 < NN) {
            int btp = blockIdx.y * 16 + tx;
            uint2 a  = tile[2 * tx][ty];
            uint2 b2 = tile[2 * tx + 1][ty];
            g_xt[n2 * BTP + btp] = make_uint4(a.x, a.y, b2.x, b2.y);
        }
    }
}

// ---------------------------------------------------------------------------
// Kernel 2: per node-pair.
//   phase 1 (192 thr): fp16 gather + f32x2 weighted agg -> fp16 A tile in smem
//   phase 2 (8 warps): D[128,12] = A[128,48] @ W[48,12] via mma.m16n8k16 (f32 acc)
//   epilogue: +bias, ReLU, stage to smem, coalesced float4 stores
// ---------------------------------------------------------------------------
__global__ void __launch_bounds__(THREADS, 4) gnn_main_kernel(
    const float* __restrict__ dists, const int* __restrict__ neighbors,
    const float* __restrict__ W, const float* __restrict__ bias,
    float* __restrict__ out)
{
    __shared__ __align__(16) __half A_s[128 * A_STRIDE];   // rows r=nl*64+b*4+c, cols t*4+h
    __shared__ __align__(16) __half WT_s[16 * A_STRIDE];   // rows n (o), cols th; rows 12-15 unused
    __shared__ ulonglong2 wp_s[NT][KK][2];                  // packed gaussian weights
    __shared__ int   nbr_s[NT][KK];
    __shared__ float b_s[DOUT];
    __shared__ __align__(16) float ys2[384 * 4];            // [(b*12+o)*2+nl][c]

    const int tid = threadIdx.x;              // 0..255
    const int n0  = blockIdx.x * NT;

    // --- Phase 0 ---
    if (tid < NT * KK) {
        int nn = tid >> 4, k = tid & 15;
        float d = dists[(n0 + nn) * KK + k];
        nbr_s[nn][k] = neighbors[(n0 + nn) * KK + k];
        float p = d * d * (1.0f / 36.0f);     // d^2 / sigma^2
        float w0 = __expf(-0.25f * p);
        float w1 = __expf(-0.50f * p);
        float w2 = __expf(-0.75f * p);
        float w3 = __expf(-p);
        wp_s[nn][k][0] = make_ulonglong2(pk(w0, w0), pk(w1, w1));
        wp_s[nn][k][1] = make_ulonglong2(pk(w2, w2), pk(w3, w3));
    }
    #pragma unroll
    for (int i = tid; i < DIN * DOUT; i += THREADS) {
        int th = i / DOUT, o = i - th * DOUT;
        WT_s[o * A_STRIDE + th] = __float2half(W[i]);      // W^T, fp16
    }
    if (tid < DOUT) b_s[tid] = bias[tid];
    __syncthreads();

    // --- Phase 1: fp16 gather + packed weighted aggregation -> fp16 A tile ---
    if (tid < 192) {
        const int nl  = tid / BTP;               // warp-uniform
        const int btp = tid - nl * BTP;
        const int bt0 = btp * 2;
        const int b0 = bt0 / TT, t0 = bt0 - b0 * TT;   // t0 even; t1 = t0+1 same b

        u64 acc[2][HH][2];                        // [bt][h][c01|c23]
        #pragma unroll
        for (int p = 0; p < 2; ++p)
            #pragma unroll
            for (int h = 0; h < HH; ++h) { acc[p][h][0] = 0ULL; acc[p][h][1] = 0ULL; }

        #pragma unroll
        for (int k = 0; k < KK; ++k) {
            uint4 raw = g_xt[nbr_s[nl][k] * BTP + btp];
            float2 p00 = h2f(raw.x);   // bt0: c0,c1
            float2 p01 = h2f(raw.y);   // bt0: c2,c3
            float2 p10 = h2f(raw.z);   // bt1: c0,c1
            float2 p11 = h2f(raw.w);   // bt1: c2,c3
            u64 x00 = pk(p00.x, p00.y);
            u64 x01 = pk(p01.x, p01.y);
            u64 x10 = pk(p10.x, p10.y);
            u64 x11 = pk(p11.x, p11.y);
            ulonglong2 wA = wp_s[nl][k][0];   // (w0,w0),(w1,w1)
            ulonglong2 wB = wp_s[nl][k][1];   // (w2,w2),(w3,w3)
            acc[0][0][0] = fma2(x00, wA.x, acc[0][0][0]);
            acc[0][0][1] = fma2(x01, wA.x, acc[0][0][1]);
            acc[0][1][0] = fma2(x00, wA.y, acc[0][1][0]);
            acc[0][1][1] = fma2(x01, wA.y, acc[0][1][1]);
            acc[0][2][0] = fma2(x00, wB.x, acc[0][2][0]);
            acc[0][2][1] = fma2(x01, wB.x, acc[0][2][1]);
            acc[0][3][0] = fma2(x00, wB.y, acc[0][3][0]);
            acc[0][3][1] = fma2(x01, wB.y, acc[0][3][1]);
            acc[1][0][0] = fma2(x10, wA.x, acc[1][0][0]);
            acc[1][0][1] = fma2(x11, wA.x, acc[1][0][1]);
            acc[1][1][0] = fma2(x10, wA.y, acc[1][1][0]);
            acc[1][1][1] = fma2(x11, wA.y, acc[1][1][1]);
            acc[1][2][0] = fma2(x10, wB.x, acc[1][2][0]);
            acc[1][2][1] = fma2(x11, wB.x, acc[1][2][1]);
            acc[1][3][0] = fma2(x10, wB.y, acc[1][3][0]);
            acc[1][3][1] = fma2(x11, wB.y, acc[1][3][1]);
        }

        // Convert to fp16 and write A rows: row r = nl*64 + b*4 + c, col = t*4 + h
        const int rowbase = nl * 64 + b0 * 4;
        #pragma unroll
        for (int bti = 0; bti < 2; ++bti) {
            int t = t0 + bti;
            float v[HH][CC];
            #pragma unroll
            for (int h = 0; h < HH; ++h) {
                float2 pA = upk(acc[bti][h][0]);
                float2 pB = upk(acc[bti][h][1]);
                v[h][0] = pA.x; v[h][1] = pA.y; v[h][2] = pB.x; v[h][3] = pB.y;
            }
            #pragma unroll
            for (int c = 0; c < CC; ++c) {
                __half2 lo2 = __floats2half2_rn(v[0][c], v[1][c]);
                __half2 hi2 = __floats2half2_rn(v[2][c], v[3][c]);
                uint2 u;
                u.x = *reinterpret_cast<unsigned*>(&lo2);
                u.y = *reinterpret_cast<unsigned*>(&hi2);
                *(uint2*)&A_s[(rowbase + c) * A_STRIDE + t * 4] = u;
            }
        }
    }
    __syncthreads();

    // --- Phase 2: tensor-core matmul. Warp w owns M-tile rows [w*16, w*16+16). ---
    {
        const int w    = tid >> 5;
        const int lane = tid & 31;
        const int gID  = lane >> 2;
        const int tig  = lane & 3;

        // B fragments: W^T[n][k] col-major pairs. 12 one-time LDS.32.
        unsigned bf[2][3][2];
        #pragma unroll
        for (int nt = 0; nt < 2; ++nt)
            #pragma unroll
            for (int s = 0; s < 3; ++s) {
                int n = nt * 8 + gID;
                bf[nt][s][0] = *(const unsigned*)&WT_s[n * A_STRIDE + s * 16 + tig * 2];
                bf[nt][s][1] = *(const unsigned*)&WT_s[n * A_STRIDE + s * 16 + tig * 2 + 8];
            }

        float d0[4] = {0.f, 0.f, 0.f, 0.f};
        float d1[4] = {0.f, 0.f, 0.f, 0.f};

        unsigned abase = sm32(A_s) +
            (w * 16 + (lane & 15)) * (A_STRIDE * 2) + (lane >> 4) * 16;
        #pragma unroll
        for (int s = 0; s < 3; ++s) {
            unsigned a0, a1, a2, a3;
            asm volatile(
                "ldmatrix.sync.aligned.m8n8.x4.shared.b16 {%0,%1,%2,%3}, [%4];"
                : "=r"(a0), "=r"(a1), "=r"(a2), "=r"(a3)
                : "r"(abase + s * 32));
            asm volatile(
                "mma.sync.aligned.m16n8k16.row.col.f32.f16.f16.f32 "
                "{%0,%1,%2,%3}, {%4,%5,%6,%7}, {%8,%9}, {%0,%1,%2,%3};"
                : "+f"(d0[0]), "+f"(d0[1]), "+f"(d0[2]), "+f"(d0[3])
                : "r"(a0), "r"(a1), "r"(a2), "r"(a3),
                  "r"(bf[0][s][0]), "r"(bf[0][s][1]));
            asm volatile(
                "mma.sync.aligned.m16n8k16.row.col.f32.f16.f16.f32 "
                "{%0,%1,%2,%3}, {%4,%5,%6,%7}, {%8,%9}, {%0,%1,%2,%3};"
                : "+f"(d1[0]), "+f"(d1[1]), "+f"(d1[2]), "+f"(d1[3])
                : "r"(a0), "r"(a1), "r"(a2), "r"(a3),
                  "r"(bf[1][s][0]), "r"(bf[1][s][1]));
        }

        // Epilogue: bias + ReLU, stage to ys2.
        #pragma unroll
        for (int nt = 0; nt < 2; ++nt) {
            const float* dd = nt ? d1 : d0;
            #pragma unroll
            for (int i = 0; i < 4; ++i) {
                int o = nt * 8 + tig * 2 + (i & 1);
                if (o < DOUT) {
                    int row = w * 16 + gID + (i >> 1) * 8;   // nl*64 + b*4 + c
                    int nl2 = row >> 6, bb = (row >> 2) & 15, cc = row & 3;
                    float val = fmaxf(dd[i] + b_s[o], 0.f);
                    ys2[(((bb * DOUT + o) << 1) + nl2) * 4 + cc] = val;
                }
            }
        }
    }
    __syncthreads();

    // --- Coalesced float4 stores ---
    float4* __restrict__ out4 = (float4*)out;
    #pragma unroll
    for (int u = tid; u < 384; u += THREADS) {
        int cell = u >> 1, j = u & 1;         // cell = b*12+o, j = node
        int bb = cell / DOUT, oo = cell - bb * DOUT;
        float4 v = *(const float4*)&ys2[u * 4];
        out4[(bb * TO + TT + oo) * NN + n0 + j] = v;
    }
}

// ---------------------------------------------------------------------------
// metadata order: x (f32), dists (f32), W (f32), b (f32), neighbors (i32);
// output f32 (7680000)
// ---------------------------------------------------------------------------
extern "C" void kernel_launch(void* const* d_in, const int* in_sizes, int n_in,
                              void* d_out, int out_size)
{
    const float* x         = (const float*)d_in[0];
    const float* dists     = (const float*)d_in[1];
    const float* W         = (const float*)d_in[2];
    const float* bias      = (const float*)d_in[3];
    const int*   neighbors = (const int*)d_in[4];
    float* out = (float*)d_out;

    dim3 tb(32, 32);
    dim3 tg((NN + 31) / 32, BT / 32);        // 157 x 6
    transpose_convert_kernel<<<tg, tb>>>(x, out);

    gnn_main_kernel<<<NN / NT, THREADS>>>(dists, neighbors, W, bias, out);
}

// round 10
// speedup vs baseline: 1.2348x; 1.0067x over previous
#include <cuda_runtime.h>
#include <cuda_fp16.h>

// Problem constants
#define NB 16            // batch B
#define TT 12            // T_IN
#define TO 24            // T_TOTAL
#define NN 5000          // nodes
#define CC 4             // channels
#define KK 16            // neighbors
#define HH 4             // heads
#define BT (NB * TT)     // 192
#define BTP (BT / 2)     // 96 bt-pairs
#define DIN (TT * HH)    // 48
#define DOUT (TO - TT)   // 12
#define NT 2             // nodes per block
#define THREADS 192
#define A_STRIDE 56      // halves per A row (112B = 7*16B -> conflict-free ldmatrix)

typedef unsigned long long u64;

// Scratch: x transposed+converted to fp16: [N][btp][8 halfs]. 7.68 MB, L2-resident.
__device__ uint4 g_xt[NN * BTP];

static __device__ __forceinline__ float2 h2f(unsigned u) {
    __half2 h = *reinterpret_cast<__half2*>(&u);
    return __half22float2(h);
}
static __device__ __forceinline__ u64 pk(float lo, float hi) {
    u64 r;
    asm("mov.b64 %0, {%1, %2};" : "=l"(r) : "f"(lo), "f"(hi));
    return r;
}
static __device__ __forceinline__ u64 fma2(u64 a, u64 b, u64 c) {
    u64 d;
    asm("fma.rn.f32x2 %0, %1, %2, %3;" : "=l"(d) : "l"(a), "l"(b), "l"(c));
    return d;
}
static __device__ __forceinline__ float2 upk(u64 v) {
    float2 f;
    asm("mov.b64 {%0, %1}, %2;" : "=f"(f.x), "=f"(f.y) : "l"(v));
    return f;
}
static __device__ __forceinline__ unsigned sm32(const void* p) {
    return (unsigned)__cvta_generic_to_shared(p);
}

// ---------------------------------------------------------------------------
// Kernel 1: x [B,T,N,C] f32 -> xt [N][btp] fp16 (transposed)  AND out[:, :12] = x
// ---------------------------------------------------------------------------
__global__ void __launch_bounds__(1024) transpose_convert_kernel(
    const float* __restrict__ x, float* __restrict__ out)
{
    __shared__ uint2 tile[32][33];
    const float4* __restrict__ x4 = (const float4*)x;
    float4* __restrict__ out4 = (float4*)out;

    int tx = threadIdx.x, ty = threadIdx.y;
    int n  = blockIdx.x * 32 + tx;
    int bt = blockIdx.y * 32 + ty;          // gridDim.y*32 == 192 exactly

    if (n < NN) {
        float4 v = x4[bt * NN + n];
        __half2 h01 = __floats2half2_rn(v.x, v.y);
        __half2 h23 = __floats2half2_rn(v.z, v.w);
        uint2 u;
        u.x = *reinterpret_cast<unsigned*>(&h01);
        u.y = *reinterpret_cast<unsigned*>(&h23);
        tile[ty][tx] = u;
        int b = bt / TT, t = bt - b * TT;
        out4[(b * TO + t) * NN + n] = v;    // out[:, :12] = x (coalesced)
    }
    __syncthreads();

    if (tx < 16) {
        int n2 = blockIdx.x * 32 + ty;
        if (n2 < NN) {
            int btp = blockIdx.y * 16 + tx;
            uint2 a  = tile[2 * tx][ty];
            uint2 b2 = tile[2 * tx + 1][ty];
            g_xt[n2 * BTP + btp] = make_uint4(a.x, a.y, b2.x, b2.y);
        }
    }
}

// ---------------------------------------------------------------------------
// Kernel 2: per node-pair, 192 threads (all active both phases).
//   phase 1: thread = (nl, btp): fp16 gather + f32x2 agg -> fp16 A tile
//   phase 2: 6 warps stride 8 m16-tiles: D[128,12] = A[128,48] @ W[48,12]
//            via mma.m16n8k16 (f32 acc); bias+ReLU; staged coalesced stores
// ---------------------------------------------------------------------------
__global__ void __launch_bounds__(THREADS, 6) gnn_main_kernel(
    const float* __restrict__ dists, const int* __restrict__ neighbors,
    const float* __restrict__ W, const float* __restrict__ bias,
    float* __restrict__ out)
{
    __shared__ __align__(16) __half A_s[128 * A_STRIDE];   // rows r=nl*64+b*4+c, cols t*4+h
    __shared__ __align__(16) __half WT_s[16 * A_STRIDE];   // rows o, cols th; rows 12-15 unused
    __shared__ ulonglong2 wp_s[NT][KK][2];                  // packed gaussian weights
    __shared__ int   nbr_s[NT][KK];
    __shared__ float b_s[DOUT];
    __shared__ __align__(16) float ys2[384 * 4];            // [(b*12+o)*2+nl][c]

    const int tid = threadIdx.x;              // 0..191
    const int n0  = blockIdx.x * NT;

    // --- Phase 0 ---
    if (tid < NT * KK) {
        int nn = tid >> 4, k = tid & 15;
        float d = dists[(n0 + nn) * KK + k];
        nbr_s[nn][k] = neighbors[(n0 + nn) * KK + k];
        float p = d * d * (1.0f / 36.0f);     // d^2 / sigma^2
        float w0 = __expf(-0.25f * p);
        float w1 = __expf(-0.50f * p);
        float w2 = __expf(-0.75f * p);
        float w3 = __expf(-p);
        wp_s[nn][k][0] = make_ulonglong2(pk(w0, w0), pk(w1, w1));
        wp_s[nn][k][1] = make_ulonglong2(pk(w2, w2), pk(w3, w3));
    }
    #pragma unroll
    for (int i = tid; i < DIN * DOUT; i += THREADS) {
        int th = i / DOUT, o = i - th * DOUT;
        WT_s[o * A_STRIDE + th] = __float2half(W[i]);      // W^T, fp16
    }
    if (tid < DOUT) b_s[tid] = bias[tid];
    __syncthreads();

    // --- Phase 1: fp16 gather + packed weighted aggregation -> fp16 A tile ---
    {
        const int nl  = tid / BTP;               // warp-uniform (96 = 3 warps)
        const int btp = tid - nl * BTP;
        const int bt0 = btp * 2;
        const int b0 = bt0 / TT, t0 = bt0 - b0 * TT;   // t0 even; t1 = t0+1 same b

        u64 acc[2][HH][2];                        // [bt][h][c01|c23]
        #pragma unroll
        for (int p = 0; p < 2; ++p)
            #pragma unroll
            for (int h = 0; h < HH; ++h) { acc[p][h][0] = 0ULL; acc[p][h][1] = 0ULL; }

        #pragma unroll
        for (int k = 0; k < KK; ++k) {
            uint4 raw = g_xt[nbr_s[nl][k] * BTP + btp];
            float2 p00 = h2f(raw.x);   // bt0: c0,c1
            float2 p01 = h2f(raw.y);   // bt0: c2,c3
            float2 p10 = h2f(raw.z);   // bt1: c0,c1
            float2 p11 = h2f(raw.w);   // bt1: c2,c3
            u64 x00 = pk(p00.x, p00.y);
            u64 x01 = pk(p01.x, p01.y);
            u64 x10 = pk(p10.x, p10.y);
            u64 x11 = pk(p11.x, p11.y);
            ulonglong2 wA = wp_s[nl][k][0];   // (w0,w0),(w1,w1)
            ulonglong2 wB = wp_s[nl][k][1];   // (w2,w2),(w3,w3)
            acc[0][0][0] = fma2(x00, wA.x, acc[0][0][0]);
            acc[0][0][1] = fma2(x01, wA.x, acc[0][0][1]);
            acc[0][1][0] = fma2(x00, wA.y, acc[0][1][0]);
            acc[0][1][1] = fma2(x01, wA.y, acc[0][1][1]);
            acc[0][2][0] = fma2(x00, wB.x, acc[0][2][0]);
            acc[0][2][1] = fma2(x01, wB.x, acc[0][2][1]);
            acc[0][3][0] = fma2(x00, wB.y, acc[0][3][0]);
            acc[0][3][1] = fma2(x01, wB.y, acc[0][3][1]);
            acc[1][0][0] = fma2(x10, wA.x, acc[1][0][0]);
            acc[1][0][1] = fma2(x11, wA.x, acc[1][0][1]);
            acc[1][1][0] = fma2(x10, wA.y, acc[1][1][0]);
            acc[1][1][1] = fma2(x11, wA.y, acc[1][1][1]);
            acc[1][2][0] = fma2(x10, wB.x, acc[1][2][0]);
            acc[1][2][1] = fma2(x11, wB.x, acc[1][2][1]);
            acc[1][3][0] = fma2(x10, wB.y, acc[1][3][0]);
            acc[1][3][1] = fma2(x11, wB.y, acc[1][3][1]);
        }

        // Convert to fp16 and write A rows: row r = nl*64 + b*4 + c, col = t*4 + h
        const int rowbase = nl * 64 + b0 * 4;
        #pragma unroll
        for (int bti = 0; bti < 2; ++bti) {
            int t = t0 + bti;
            float v[HH][CC];
            #pragma unroll
            for (int h = 0; h < HH; ++h) {
                float2 pA = upk(acc[bti][h][0]);
                float2 pB = upk(acc[bti][h][1]);
                v[h][0] = pA.x; v[h][1] = pA.y; v[h][2] = pB.x; v[h][3] = pB.y;
            }
            #pragma unroll
            for (int c = 0; c < CC; ++c) {
                __half2 lo2 = __floats2half2_rn(v[0][c], v[1][c]);
                __half2 hi2 = __floats2half2_rn(v[2][c], v[3][c]);
                uint2 u;
                u.x = *reinterpret_cast<unsigned*>(&lo2);
                u.y = *reinterpret_cast<unsigned*>(&hi2);
                *(uint2*)&A_s[(rowbase + c) * A_STRIDE + t * 4] = u;
            }
        }
    }
    __syncthreads();

    // --- Phase 2: tensor-core matmul. 6 warps stride the 8 m16-tiles. ---
    {
        const int w    = tid >> 5;                // 0..5
        const int lane = tid & 31;
        const int gID  = lane >> 2;
        const int tig  = lane & 3;

        // B fragments: W^T[n][k] col-major pairs, tile-invariant.
        unsigned bf[2][3][2];
        #pragma unroll
        for (int nt = 0; nt < 2; ++nt)
            #pragma unroll
            for (int s = 0; s < 3; ++s) {
                int n = nt * 8 + gID;
                bf[nt][s][0] = *(const unsigned*)&WT_s[n * A_STRIDE + s * 16 + tig * 2];
                bf[nt][s][1] = *(const unsigned*)&WT_s[n * A_STRIDE + s * 16 + tig * 2 + 8];
            }

        for (int tile = w; tile < 8; tile += 6) {
            float d0[4] = {0.f, 0.f, 0.f, 0.f};
            float d1[4] = {0.f, 0.f, 0.f, 0.f};

            unsigned abase = sm32(A_s) +
                (tile * 16 + (lane & 15)) * (A_STRIDE * 2) + (lane >> 4) * 16;
            #pragma unroll
            for (int s = 0; s < 3; ++s) {
                unsigned a0, a1, a2, a3;
                asm volatile(
                    "ldmatrix.sync.aligned.m8n8.x4.shared.b16 {%0,%1,%2,%3}, [%4];"
                    : "=r"(a0), "=r"(a1), "=r"(a2), "=r"(a3)
                    : "r"(abase + s * 32));
                asm volatile(
                    "mma.sync.aligned.m16n8k16.row.col.f32.f16.f16.f32 "
                    "{%0,%1,%2,%3}, {%4,%5,%6,%7}, {%8,%9}, {%0,%1,%2,%3};"
                    : "+f"(d0[0]), "+f"(d0[1]), "+f"(d0[2]), "+f"(d0[3])
                    : "r"(a0), "r"(a1), "r"(a2), "r"(a3),
                      "r"(bf[0][s][0]), "r"(bf[0][s][1]));
                asm volatile(
                    "mma.sync.aligned.m16n8k16.row.col.f32.f16.f16.f32 "
                    "{%0,%1,%2,%3}, {%4,%5,%6,%7}, {%8,%9}, {%0,%1,%2,%3};"
                    : "+f"(d1[0]), "+f"(d1[1]), "+f"(d1[2]), "+f"(d1[3])
                    : "r"(a0), "r"(a1), "r"(a2), "r"(a3),
                      "r"(bf[1][s][0]), "r"(bf[1][s][1]));
            }

            // Epilogue: bias + ReLU, stage to ys2.
            #pragma unroll
            for (int nt = 0; nt < 2; ++nt) {
                const float* dd = nt ? d1 : d0;
                #pragma unroll
                for (int i = 0; i < 4; ++i) {
                    int o = nt * 8 + tig * 2 + (i & 1);
                    if (o < DOUT) {
                        int row = tile * 16 + gID + (i >> 1) * 8;   // nl*64 + b*4 + c
                        int nl2 = row >> 6, bb = (row >> 2) & 15, cc = row & 3;
                        float val = fmaxf(dd[i] + b_s[o], 0.f);
                        ys2[(((bb * DOUT + o) << 1) + nl2) * 4 + cc] = val;
                    }
                }
            }
        }
    }
    __syncthreads();

    // --- Coalesced float4 stores: 384 cells / 192 threads = 2 each ---
    float4* __restrict__ out4 = (float4*)out;
    #pragma unroll
    for (int it = 0; it < 2; ++it) {
        int u = it * THREADS + tid;           // 0..383
        int cell = u >> 1, j = u & 1;         // cell = b*12+o, j = node
        int bb = cell / DOUT, oo = cell - bb * DOUT;
        float4 v = *(const float4*)&ys2[u * 4];
        out4[(bb * TO + TT + oo) * NN + n0 + j] = v;
    }
}

// ---------------------------------------------------------------------------
// metadata order: x (f32), dists (f32), W (f32), b (f32), neighbors (i32);
// output f32 (7680000)
// ---------------------------------------------------------------------------
extern "C" void kernel_launch(void* const* d_in, const int* in_sizes, int n_in,
                              void* d_out, int out_size)
{
    const float* x         = (const float*)d_in[0];
    const float* dists     = (const float*)d_in[1];
    const float* W         = (const float*)d_in[2];
    const float* bias      = (const float*)d_in[3];
    const int*   neighbors = (const int*)d_in[4];
    float* out = (float*)d_out;

    dim3 tb(32, 32);
    dim3 tg((NN + 31) / 32, BT / 32);        // 157 x 6
    transpose_convert_kernel<<<tg, tb>>>(x, out);

    gnn_main_kernel<<<NN / NT, THREADS>>>(dists, neighbors, W, bias, out);
}